// round 7
// baseline (speedup 1.0000x reference)
#include <cuda_runtime.h>
#include <math.h>

#define BB      16
#define HWN     589824            // 768*768
#define KBINS   8192              // 2^13 bins; counters = 1 MB, L2-resident
#define KH      (KBINS / 2)       // packed u16-pair words per histogram
#define HBLK    36                // hist blocks per sample
#define HTH     512
#define EPB     (HWN / HBLK)      // 16384 elements per block (u16-safe)
#define HITER   (EPB / (HTH * 4)) // 8 float4 iterations per thread
#define FTH     1024
#define SLICES  8                 // merge slices per sample -> 128 blocks total
#define RPT     (HWN / (SLICES * FTH))   // 72 ranks per fused-kernel thread

// Scratch (allocation-free rule: __device__ globals)
__device__ unsigned int       g_cnt[2][BB][KBINS];   // raw histograms (scan happens in smem)
__device__ unsigned long long g_acc;
__device__ unsigned int       g_done = 0;

// ---------------------------------------------------------------------------
// 1) sigmoid(x1-x0) + SMEM-privatized histograms (u16-packed), flush as u64 REDs
// ---------------------------------------------------------------------------
__global__ void __launch_bounds__(HTH, 4)
hist_kernel(const float* __restrict__ x, const float* __restrict__ t) {
    __shared__ unsigned int sp[KH];
    __shared__ unsigned int sq[KH];

    const int tid = threadIdx.x;
    const int b   = blockIdx.y;

    if (blockIdx.x == 0 && b == 0 && tid == 0) g_acc = 0ull;   // for the fused kernel

    for (int i = tid; i < KH; i += HTH) { sp[i] = 0u; sq[i] = 0u; }
    __syncthreads();

    const size_t off = (size_t)blockIdx.x * EPB;
    const float* __restrict__ x0p = x + (size_t)b * 2 * HWN + off;
    const float* __restrict__ x1p = x0p + HWN;
    const float* __restrict__ tp  = t + (size_t)b * HWN + off;
    const float kf = (float)KBINS;

    #pragma unroll
    for (int it = 0; it < HITER; ++it) {
        int i4 = (it * HTH + tid) * 4;
        float4 a0 = *reinterpret_cast<const float4*>(&x0p[i4]);
        float4 a1 = *reinterpret_cast<const float4*>(&x1p[i4]);
        float4 tv = *reinterpret_cast<const float4*>(&tp[i4]);
        #pragma unroll
        for (int j = 0; j < 4; ++j) {
            float d  = (j == 0 ? a0.x - a1.x : j == 1 ? a0.y - a1.y : j == 2 ? a0.z - a1.z : a0.w - a1.w);
            float v  = __fdividef(1.0f, 1.0f + __expf(d));
            int bp = (int)(v * kf);
            bp = bp > KBINS - 1 ? KBINS - 1 : (bp < 0 ? 0 : bp);
            atomicAdd(&sp[bp >> 1], 1u << ((bp & 1) << 4));
            float tj = (j == 0 ? tv.x : j == 1 ? tv.y : j == 2 ? tv.z : tv.w);
            int bq = (int)(tj * kf);
            bq = bq > KBINS - 1 ? KBINS - 1 : (bq < 0 ? 0 : bq);
            atomicAdd(&sq[bq >> 1], 1u << ((bq & 1) << 4));
        }
    }
    __syncthreads();

    unsigned long long* __restrict__ gp = reinterpret_cast<unsigned long long*>(&g_cnt[0][b][0]);
    unsigned long long* __restrict__ gq = reinterpret_cast<unsigned long long*>(&g_cnt[1][b][0]);
    for (int w = tid; w < KH; w += HTH) {
        unsigned v = sp[w];
        if (v) atomicAdd(&gp[w], (unsigned long long)(v & 0xFFFFu) |
                                 ((unsigned long long)(v >> 16) << 32));
        v = sq[w];
        if (v) atomicAdd(&gq[w], (unsigned long long)(v & 0xFFFFu) |
                                 ((unsigned long long)(v >> 16) << 32));
    }
}

// ---------------------------------------------------------------------------
// 2) fused: per-(sample,slice) block: scan rows to smem + merge slice + finalize
// ---------------------------------------------------------------------------
__device__ __forceinline__ void scan_row_to_smem(const unsigned* __restrict__ row,
                                                 unsigned* __restrict__ dst,
                                                 unsigned* warpsums, int tid) {
    int base = tid * 8;
    uint4 v0 = *reinterpret_cast<const uint4*>(&row[base + 0]);
    uint4 v1 = *reinterpret_cast<const uint4*>(&row[base + 4]);

    v0.y += v0.x; v0.z += v0.y; v0.w += v0.z;
    v1.x += v0.w; v1.y += v1.x; v1.z += v1.y; v1.w += v1.z;
    unsigned tot = v1.w;

    unsigned lane = tid & 31, wid = tid >> 5;
    unsigned s = tot;
    #pragma unroll
    for (int o = 1; o < 32; o <<= 1) {
        unsigned n = __shfl_up_sync(0xFFFFFFFFu, s, o);
        if (lane >= o) s += n;
    }
    if (lane == 31) warpsums[wid] = s;
    __syncthreads();
    if (wid == 0) {
        unsigned ws = warpsums[lane];
        #pragma unroll
        for (int o = 1; o < 32; o <<= 1) {
            unsigned n = __shfl_up_sync(0xFFFFFFFFu, ws, o);
            if (lane >= o) ws += n;
        }
        warpsums[lane] = ws;
    }
    __syncthreads();

    unsigned prefix = (s - tot) + (wid ? warpsums[wid - 1] : 0u);
    v0.x += prefix; v0.y += prefix; v0.z += prefix; v0.w += prefix;
    v1.x += prefix; v1.y += prefix; v1.z += prefix; v1.w += prefix;
    *reinterpret_cast<uint4*>(&dst[base + 0]) = v0;
    *reinterpret_cast<uint4*>(&dst[base + 4]) = v1;
}

__device__ __forceinline__ int upper_bound_sm(const unsigned* __restrict__ cdf, unsigned r) {
    int lo = 0, hi = KBINS;
    while (lo < hi) {
        int mid = (lo + hi) >> 1;
        if (cdf[mid] <= r) lo = mid + 1; else hi = mid;
    }
    return lo;
}

// Galloping advance: given cdf[k] <= r (and r < HWN so cdf[KBINS-1] > r),
// return smallest k' with cdf[k'] > r. Exponential probe + binary refine:
// O(log gap) instead of O(gap) dependent LDS through empty-bin runs.
__device__ __forceinline__ int advance_sm(const unsigned* __restrict__ cdf, int k, unsigned r) {
    int lo = k;                       // cdf[lo] <= r
    int step = 1;
    while (lo + step < KBINS && cdf[lo + step] <= r) { lo += step; step <<= 1; }
    int hi = lo + step;
    if (hi > KBINS - 1) hi = KBINS - 1;   // cdf[KBINS-1] = HWN > r
    while (hi - lo > 1) {
        int mid = (lo + hi) >> 1;
        if (cdf[mid] <= r) lo = mid; else hi = mid;
    }
    return hi;
}

__device__ __forceinline__ unsigned long long warpReduceU64(unsigned long long v) {
    #pragma unroll
    for (int o = 16; o > 0; o >>= 1) v += __shfl_down_sync(0xFFFFFFFFu, v, o);
    return v;
}

__global__ void __launch_bounds__(FTH, 1)
fused_kernel(float* __restrict__ out) {
    extern __shared__ unsigned sh[];                 // sp[KBINS] | sq[KBINS]
    unsigned* sp = sh;
    unsigned* sq = sh + KBINS;
    __shared__ unsigned warpsums[32];
    __shared__ unsigned long long shred[32];

    const int b     = blockIdx.y;
    const int slice = blockIdx.x;
    const int tid   = threadIdx.x;

    scan_row_to_smem(&g_cnt[0][b][0], sp, warpsums, tid);
    __syncthreads();
    scan_row_to_smem(&g_cnt[1][b][0], sq, warpsums, tid);
    __syncthreads();

    // bin-space merge of this block's rank slice
    unsigned r0 = ((unsigned)slice * FTH + tid) * RPT;
    unsigned r1 = r0 + RPT;
    int kp = upper_bound_sm(sp, r0);
    int kq = upper_bound_sm(sq, r0);
    unsigned cp = sp[kp];
    unsigned cq = sq[kq];

    unsigned long long local = 0ull;
    unsigned r = r0;
    while (r < r1) {
        unsigned next = cp < cq ? cp : cq;
        next = next < r1 ? next : r1;
        int dk = kp - kq;
        local += (unsigned long long)(next - r) * (unsigned long long)(dk * dk);
        r = next;
        if (r >= r1) break;
        if (cp <= r) { kp = advance_sm(sp, kp, r); cp = sp[kp]; }
        if (cq <= r) { kq = advance_sm(sq, kq, r); cq = sq[kq]; }
    }

    local = warpReduceU64(local);
    int lane = tid & 31, wid = tid >> 5;
    if (lane == 0) shred[wid] = local;
    __syncthreads();
    if (wid == 0) {
        unsigned long long v = (lane < (FTH >> 5)) ? shred[lane] : 0ull;
        v = warpReduceU64(v);
        if (lane == 0) {
            atomicAdd(&g_acc, v);
            __threadfence();
            unsigned old = atomicAdd(&g_done, 1u);
            if (old == BB * SLICES - 1) {             // last block finalizes
                g_done = 0;                           // self-reset for graph replay
                unsigned long long total = *(volatile unsigned long long*)&g_acc;
                const double ds = 1.0 / (double)KBINS;
                out[0] = (float)((double)total * ds * ds / ((double)BB * (double)HWN));
            }
        }
    }
}

// ---------------------------------------------------------------------------
extern "C" void kernel_launch(void* const* d_in, const int* in_sizes, int n_in,
                              void* d_out, int out_size) {
    const float* x = (const float*)d_in[0];   // [16, 2, 768, 768]
    const float* t = (const float*)d_in[1];   // [16, 768, 768]
    float* out = (float*)d_out;               // scalar

    void* cnt_ptr = nullptr;
    cudaGetSymbolAddress(&cnt_ptr, g_cnt);
    cudaMemsetAsync(cnt_ptr, 0, sizeof(unsigned int) * 2 * BB * KBINS, 0);

    const int smem_bytes = 2 * KBINS * sizeof(unsigned);  // 64 KB
    static int attr_set = 0;
    if (!attr_set) {
        cudaFuncSetAttribute(fused_kernel, cudaFuncAttributeMaxDynamicSharedMemorySize,
                             smem_bytes);
        attr_set = 1;
    }

    hist_kernel<<<dim3(HBLK, BB), HTH>>>(x, t);
    fused_kernel<<<dim3(SLICES, BB), FTH, smem_bytes>>>(out);
}

// round 8
// speedup vs baseline: 1.1313x; 1.1313x over previous
#include <cuda_runtime.h>
#include <math.h>

#define BB      16
#define HWN     589824            // 768*768
#define KBINS   8192              // 2^13 bins; counters = 1 MB, L2-resident
#define KH      (KBINS / 2)       // packed u16-pair words per histogram
#define HBLK    36                // hist blocks per sample
#define HTH     512
#define EPB     (HWN / HBLK)      // 16384 elements per block (u16-safe)
#define HITER   (EPB / (HTH * 4)) // 8 float4 iterations per thread
#define FTH     1024
#define SLICES  8                 // event slices per sample -> 128 blocks total
#define EVENTS  (2 * KBINS)       // merged CDF events per sample (16384)
#define EPT     (EVENTS / (SLICES * FTH))   // 2 events per thread

// Scratch (allocation-free rule: __device__ globals)
__device__ unsigned int       g_cnt[2][BB][KBINS];   // raw histograms (scan happens in smem)
__device__ unsigned long long g_acc;
__device__ unsigned int       g_done = 0;

// ---------------------------------------------------------------------------
// 1) sigmoid(x1-x0) + SMEM-privatized histograms (u16-packed), flush as u64 REDs
// ---------------------------------------------------------------------------
__global__ void __launch_bounds__(HTH, 4)
hist_kernel(const float* __restrict__ x, const float* __restrict__ t) {
    __shared__ unsigned int sp[KH];
    __shared__ unsigned int sq[KH];

    const int tid = threadIdx.x;
    const int b   = blockIdx.y;

    if (blockIdx.x == 0 && b == 0 && tid == 0) g_acc = 0ull;   // for the fused kernel

    for (int i = tid; i < KH; i += HTH) { sp[i] = 0u; sq[i] = 0u; }
    __syncthreads();

    const size_t off = (size_t)blockIdx.x * EPB;
    const float* __restrict__ x0p = x + (size_t)b * 2 * HWN + off;
    const float* __restrict__ x1p = x0p + HWN;
    const float* __restrict__ tp  = t + (size_t)b * HWN + off;
    const float kf = (float)KBINS;

    #pragma unroll
    for (int it = 0; it < HITER; ++it) {
        int i4 = (it * HTH + tid) * 4;
        float4 a0 = *reinterpret_cast<const float4*>(&x0p[i4]);
        float4 a1 = *reinterpret_cast<const float4*>(&x1p[i4]);
        float4 tv = *reinterpret_cast<const float4*>(&tp[i4]);
        #pragma unroll
        for (int j = 0; j < 4; ++j) {
            float d  = (j == 0 ? a0.x - a1.x : j == 1 ? a0.y - a1.y : j == 2 ? a0.z - a1.z : a0.w - a1.w);
            float v  = __fdividef(1.0f, 1.0f + __expf(d));
            int bp = (int)(v * kf);
            bp = bp > KBINS - 1 ? KBINS - 1 : (bp < 0 ? 0 : bp);
            atomicAdd(&sp[bp >> 1], 1u << ((bp & 1) << 4));
            float tj = (j == 0 ? tv.x : j == 1 ? tv.y : j == 2 ? tv.z : tv.w);
            int bq = (int)(tj * kf);
            bq = bq > KBINS - 1 ? KBINS - 1 : (bq < 0 ? 0 : bq);
            atomicAdd(&sq[bq >> 1], 1u << ((bq & 1) << 4));
        }
    }
    __syncthreads();

    unsigned long long* __restrict__ gp = reinterpret_cast<unsigned long long*>(&g_cnt[0][b][0]);
    unsigned long long* __restrict__ gq = reinterpret_cast<unsigned long long*>(&g_cnt[1][b][0]);
    for (int w = tid; w < KH; w += HTH) {
        unsigned v = sp[w];
        if (v) atomicAdd(&gp[w], (unsigned long long)(v & 0xFFFFu) |
                                 ((unsigned long long)(v >> 16) << 32));
        v = sq[w];
        if (v) atomicAdd(&gq[w], (unsigned long long)(v & 0xFFFFu) |
                                 ((unsigned long long)(v >> 16) << 32));
    }
}

// ---------------------------------------------------------------------------
// 2) fused: scan rows to smem + merged-event sum + last-block finalize
// ---------------------------------------------------------------------------
__device__ __forceinline__ void scan_row_to_smem(const unsigned* __restrict__ row,
                                                 unsigned* __restrict__ dst,
                                                 unsigned* warpsums, int tid) {
    int base = tid * 8;
    uint4 v0 = *reinterpret_cast<const uint4*>(&row[base + 0]);
    uint4 v1 = *reinterpret_cast<const uint4*>(&row[base + 4]);

    v0.y += v0.x; v0.z += v0.y; v0.w += v0.z;
    v1.x += v0.w; v1.y += v1.x; v1.z += v1.y; v1.w += v1.z;
    unsigned tot = v1.w;

    unsigned lane = tid & 31, wid = tid >> 5;
    unsigned s = tot;
    #pragma unroll
    for (int o = 1; o < 32; o <<= 1) {
        unsigned n = __shfl_up_sync(0xFFFFFFFFu, s, o);
        if (lane >= o) s += n;
    }
    if (lane == 31) warpsums[wid] = s;
    __syncthreads();
    if (wid == 0) {
        unsigned ws = warpsums[lane];
        #pragma unroll
        for (int o = 1; o < 32; o <<= 1) {
            unsigned n = __shfl_up_sync(0xFFFFFFFFu, ws, o);
            if (lane >= o) ws += n;
        }
        warpsums[lane] = ws;
    }
    __syncthreads();

    unsigned prefix = (s - tot) + (wid ? warpsums[wid - 1] : 0u);
    v0.x += prefix; v0.y += prefix; v0.z += prefix; v0.w += prefix;
    v1.x += prefix; v1.y += prefix; v1.z += prefix; v1.w += prefix;
    *reinterpret_cast<uint4*>(&dst[base + 0]) = v0;
    *reinterpret_cast<uint4*>(&dst[base + 4]) = v1;
}

__device__ __forceinline__ unsigned long long warpReduceU64(unsigned long long v) {
    #pragma unroll
    for (int o = 16; o > 0; o >>= 1) v += __shfl_down_sync(0xFFFFFFFFu, v, o);
    return v;
}

__global__ void __launch_bounds__(FTH, 1)
fused_kernel(float* __restrict__ out) {
    extern __shared__ unsigned sh[];                 // sp[KBINS] | sq[KBINS]
    unsigned* sp = sh;
    unsigned* sq = sh + KBINS;
    __shared__ unsigned warpsums[32];
    __shared__ unsigned long long shred[32];

    const int b     = blockIdx.y;
    const int slice = blockIdx.x;
    const int tid   = threadIdx.x;

    scan_row_to_smem(&g_cnt[0][b][0], sp, warpsums, tid);
    __syncthreads();
    scan_row_to_smem(&g_cnt[1][b][0], sq, warpsums, tid);
    __syncthreads();

    // ---- merged-event sum over this thread's EPT events -------------------
    // merged multiset of {sp[k]} and {sq[k]} (ties: p before q); element i
    // with prefix counts (a,b) contributes (v_{i+1}-v_i)*(a-b)^2.
    const int i0 = (slice * FTH + tid) * EPT;

    // merge-path diagonal search: smallest a with (b==0 || a==KBINS || sq[b-1] < sp[a])
    int lo = i0 - KBINS; lo = lo < 0 ? 0 : lo;
    int hi = i0 < KBINS ? i0 : KBINS;
    while (lo < hi) {
        int a = (lo + hi) >> 1;
        int bq = i0 - a;
        if (bq > 0 && a < KBINS && sq[bq - 1] >= sp[a]) lo = a + 1;
        else hi = a;
    }
    int a = lo, bq = i0 - lo;

    unsigned long long local = 0ull;
    #pragma unroll
    for (int e = 0; e < EPT; ++e) {
        unsigned vp = (a  < KBINS) ? sp[a]  : 0xFFFFFFFFu;
        unsigned vq = (bq < KBINS) ? sq[bq] : 0xFFFFFFFFu;
        unsigned vcur;
        if (vp <= vq) { vcur = vp; ++a; } else { vcur = vq; ++bq; }
        unsigned np = (a  < KBINS) ? sp[a]  : 0xFFFFFFFFu;
        unsigned nq = (bq < KBINS) ? sq[bq] : 0xFFFFFFFFu;
        unsigned vnext = np < nq ? np : nq;
        if (vnext != 0xFFFFFFFFu) {
            int dk = a - bq;
            local += (unsigned long long)(vnext - vcur) * (unsigned long long)(dk * dk);
        }
    }

    local = warpReduceU64(local);
    int lane = tid & 31, wid = tid >> 5;
    if (lane == 0) shred[wid] = local;
    __syncthreads();
    if (wid == 0) {
        unsigned long long v = (lane < (FTH >> 5)) ? shred[lane] : 0ull;
        v = warpReduceU64(v);
        if (lane == 0) {
            atomicAdd(&g_acc, v);
            __threadfence();
            unsigned old = atomicAdd(&g_done, 1u);
            if (old == BB * SLICES - 1) {             // last block finalizes
                g_done = 0;                           // self-reset for graph replay
                unsigned long long total = *(volatile unsigned long long*)&g_acc;
                const double ds = 1.0 / (double)KBINS;
                out[0] = (float)((double)total * ds * ds / ((double)BB * (double)HWN));
            }
        }
    }
}

// ---------------------------------------------------------------------------
extern "C" void kernel_launch(void* const* d_in, const int* in_sizes, int n_in,
                              void* d_out, int out_size) {
    const float* x = (const float*)d_in[0];   // [16, 2, 768, 768]
    const float* t = (const float*)d_in[1];   // [16, 768, 768]
    float* out = (float*)d_out;               // scalar

    void* cnt_ptr = nullptr;
    cudaGetSymbolAddress(&cnt_ptr, g_cnt);
    cudaMemsetAsync(cnt_ptr, 0, sizeof(unsigned int) * 2 * BB * KBINS, 0);

    const int smem_bytes = 2 * KBINS * sizeof(unsigned);  // 64 KB
    static int attr_set = 0;
    if (!attr_set) {
        cudaFuncSetAttribute(fused_kernel, cudaFuncAttributeMaxDynamicSharedMemorySize,
                             smem_bytes);
        attr_set = 1;
    }

    hist_kernel<<<dim3(HBLK, BB), HTH>>>(x, t);
    fused_kernel<<<dim3(SLICES, BB), FTH, smem_bytes>>>(out);
}